// round 16
// baseline (speedup 1.0000x reference)
#include <cuda_runtime.h>
#include <cuda_fp16.h>
#include <cstdint>

// DistMult forward scoring:
//   score[e] = sum_d h[src[e],d] * fwd_rel[etype[e],d] * h[dst[e],d]
// E = 640000, D = 128. Index arrays are int32 on device (JAX x64 disabled).
//
// R16 = R15 (27.07us; main kernel at the chip-wide LTS byte cap:
// ~340MB @ ~12.8TB/s) + programmatic dependent launch (PDL) to overlap the
// cvt prologue's tail with the main kernel's launch + index loads:
//   - cvt calls cudaTriggerProgrammaticLaunchCompletion() after its stores
//   - main loads src/dst/etype (inputs, independent of cvt) first, then
//     cudaGridDependencySynchronize() before touching g_h16/g_w16
//   - main is launched with cudaLaunchAttributeProgrammaticStreamSerialization
// Everything else is byte-identical to R15.

#define EMB_DIM   128
#define FULL      0xffffffffu
#define MAX_NODES 16384
#define MAX_RELS  1024

__device__ __half g_h16[MAX_NODES * EMB_DIM];   // 4 MB scratch
__device__ __half g_w16[MAX_RELS  * EMB_DIM];   // 256 KB scratch

// ---- merged fp32 -> fp16 conversion, 16 floats (2 uint4 out) per thread ----
__global__ __launch_bounds__(256) void cvt_merged_kernel(
    const float* __restrict__ h,
    const float* __restrict__ w,
    int n_h16, int n_tot16)
{
    const int i = blockIdx.x * blockDim.x + threadIdx.x;
    if (i < n_tot16) {
        const float4* in;
        uint4* out;
        if (i < n_h16) {
            in  = reinterpret_cast<const float4*>(h) + i * 4;
            out = reinterpret_cast<uint4*>(g_h16) + i * 2;
        } else {
            const int j = i - n_h16;
            in  = reinterpret_cast<const float4*>(w) + j * 4;
            out = reinterpret_cast<uint4*>(g_w16) + j * 2;
        }

        // 4 independent streaming loads (MLP=4).
        const float4 v0 = __ldcs(in + 0);
        const float4 v1 = __ldcs(in + 1);
        const float4 v2 = __ldcs(in + 2);
        const float4 v3 = __ldcs(in + 3);

        __half2 p0 = __floats2half2_rn(v0.x, v0.y);
        __half2 p1 = __floats2half2_rn(v0.z, v0.w);
        __half2 p2 = __floats2half2_rn(v1.x, v1.y);
        __half2 p3 = __floats2half2_rn(v1.z, v1.w);
        __half2 p4 = __floats2half2_rn(v2.x, v2.y);
        __half2 p5 = __floats2half2_rn(v2.z, v2.w);
        __half2 p6 = __floats2half2_rn(v3.x, v3.y);
        __half2 p7 = __floats2half2_rn(v3.z, v3.w);

        uint4 o0, o1;
        o0.x = *reinterpret_cast<uint32_t*>(&p0);
        o0.y = *reinterpret_cast<uint32_t*>(&p1);
        o0.z = *reinterpret_cast<uint32_t*>(&p2);
        o0.w = *reinterpret_cast<uint32_t*>(&p3);
        o1.x = *reinterpret_cast<uint32_t*>(&p4);
        o1.y = *reinterpret_cast<uint32_t*>(&p5);
        o1.z = *reinterpret_cast<uint32_t*>(&p6);
        o1.w = *reinterpret_cast<uint32_t*>(&p7);
        out[0] = o0;
        out[1] = o1;
    }
    // Allow the dependent (main) kernel to begin launching; its
    // gridDependencySynchronize still orders g_h16/g_w16 visibility.
    cudaTriggerProgrammaticLaunchCompletion();
}

// acc2 += (u*w) * v over one uint4 triple (8 halves = 4 half2), all fp16x2.
__device__ __forceinline__ __half2 fma8_h2(uint4 u, uint4 w, uint4 v, __half2 acc2)
{
    const uint32_t* pu = reinterpret_cast<const uint32_t*>(&u);
    const uint32_t* pw = reinterpret_cast<const uint32_t*>(&w);
    const uint32_t* pv = reinterpret_cast<const uint32_t*>(&v);
    #pragma unroll
    for (int k = 0; k < 4; k++) {
        __half2 hu = *reinterpret_cast<const __half2*>(pu + k);
        __half2 hw = *reinterpret_cast<const __half2*>(pw + k);
        __half2 hv = *reinterpret_cast<const __half2*>(pv + k);
        acc2 = __hfma2(__hmul2(hu, hw), hv, acc2);   // 2 instrs per half2
    }
    return acc2;
}

__global__ __launch_bounds__(256, 7) void distmult_fp16_kernel(
    const int* __restrict__ src,
    const int* __restrict__ dst,
    const int* __restrict__ etype,
    float* __restrict__ out,
    int n_edges)
{
    const int warp  = (blockIdx.x * blockDim.x + threadIdx.x) >> 5;
    const int lane  = threadIdx.x & 31;
    const int group = lane >> 3;   // 0..3 : edge within the quad
    const int sl    = lane & 7;    // 0..7 : sub-lane within the edge

    int e = warp * 4 + group;
    const bool valid = (e < n_edges);
    const bool work  = (warp * 4 < n_edges);
    const int ec = valid ? e : (n_edges - 1);

    // Index loads: input buffers, independent of the cvt kernel's writes —
    // issue them BEFORE the grid dependency sync to overlap cvt's tail.
    int s = 0, d = 0, t = 0;
    if (work) {
        s = src[ec];
        d = dst[ec];
        t = etype[ec];
    }

    // Wait for the cvt kernel's g_h16/g_w16 writes to be visible.
    cudaGridDependencySynchronize();

    if (!work) return;

    const uint4* __restrict__ RU =
        reinterpret_cast<const uint4*>(g_h16 + (size_t)s * EMB_DIM);
    const uint4* __restrict__ RV =
        reinterpret_cast<const uint4*>(g_h16 + (size_t)d * EMB_DIM);
    const uint4* __restrict__ RW =
        reinterpret_cast<const uint4*>(g_w16 + (size_t)t * EMB_DIM);

    // Two independent fp16x2 accumulators: each element sums only 4 terms,
    // keeping fp16 accumulation error small; combined once in fp32 below.
    const uint4 au0 = __ldcg(RU + sl);        // h: L2-only
    const uint4 av0 = __ldcg(RV + sl);
    const uint4 aw0 = __ldg (RW + sl);        // rel: L1-resident
    const uint4 au1 = __ldcg(RU + sl + 8);
    const uint4 av1 = __ldcg(RV + sl + 8);
    const uint4 aw1 = __ldg (RW + sl + 8);

    __half2 z = __float2half2_rn(0.0f);
    __half2 acc2a = fma8_h2(au0, aw0, av0, z);
    __half2 acc2b = fma8_h2(au1, aw1, av1, z);

    const float2 fa = __half22float2(acc2a);
    const float2 fb = __half22float2(acc2b);
    float acc = (fa.x + fa.y) + (fb.x + fb.y);

    // Reduce across the 8 sub-lanes of each group.
    acc += __shfl_xor_sync(FULL, acc, 4);
    acc += __shfl_xor_sync(FULL, acc, 2);
    acc += __shfl_xor_sync(FULL, acc, 1);

    if (valid && sl == 0) out[e] = acc;     // 4 contiguous floats / warp
}

// ---- fp32 fallback (R6 kernel) for unexpected dimensions ----
__global__ __launch_bounds__(256, 8) void distmult_fp32_kernel(
    const float* __restrict__ h,
    const int* __restrict__ src,
    const int* __restrict__ dst,
    const int* __restrict__ etype,
    const float* __restrict__ fwd_rel,
    float* __restrict__ out,
    int n_edges)
{
    const int warp  = (blockIdx.x * blockDim.x + threadIdx.x) >> 5;
    const int lane  = threadIdx.x & 31;
    const int group = lane >> 3;
    const int sl    = lane & 7;

    int e = warp * 4 + group;
    const bool valid = (e < n_edges);
    if (warp * 4 >= n_edges) return;
    const int ec = valid ? e : (n_edges - 1);

    const int s = src[ec];
    const int d = dst[ec];
    const int t = etype[ec];

    const float4* __restrict__ hu = reinterpret_cast<const float4*>(h + (size_t)s * EMB_DIM);
    const float4* __restrict__ hv = reinterpret_cast<const float4*>(h + (size_t)d * EMB_DIM);
    const float4* __restrict__ wr = reinterpret_cast<const float4*>(fwd_rel + (size_t)t * EMB_DIM);

    float acc = 0.0f;
    #pragma unroll
    for (int j = 0; j < 4; j++) {
        const int idx = sl + j * 8;
        const float4 a = __ldcg(hu + idx);
        const float4 c = __ldcg(hv + idx);
        const float4 b = __ldg(wr + idx);
        float p = a.x * b.x * c.x;
        p = fmaf(a.y * b.y, c.y, p);
        p = fmaf(a.z * b.z, c.z, p);
        p = fmaf(a.w * b.w, c.w, p);
        acc += p;
    }
    acc += __shfl_xor_sync(FULL, acc, 4);
    acc += __shfl_xor_sync(FULL, acc, 2);
    acc += __shfl_xor_sync(FULL, acc, 1);
    if (valid && sl == 0) out[e] = acc;
}

extern "C" void kernel_launch(void* const* d_in, const int* in_sizes, int n_in,
                              void* d_out, int out_size)
{
    const float* h       = (const float*)d_in[0];
    const int*   src     = (const int*)d_in[1];
    const int*   dst     = (const int*)d_in[2];
    const int*   etype   = (const int*)d_in[3];
    const float* fwd_rel = (const float*)d_in[4];
    // d_in[5] = rev_rel, unused in forward scoring.
    float* out = (float*)d_out;

    const int n_edges = in_sizes[1];   // src element count
    const int h_elems = in_sizes[0];   // n_nodes * 128
    const int w_elems = in_sizes[4];   // num_rels * 128

    const int threads = 256;
    const int blocks  = (n_edges + 31) / 32;   // 8 warps x 4 edges per block

    if (h_elems > MAX_NODES * EMB_DIM || w_elems > MAX_RELS * EMB_DIM ||
        (h_elems & 15) || (w_elems & 15)) {
        // Unexpected dims: proven fp32 path.
        distmult_fp32_kernel<<<blocks, threads>>>(h, src, dst, etype, fwd_rel,
                                                  out, n_edges);
        return;
    }

    // Prologue: merged fp32 -> fp16 staging (one launch, 16 floats/thread).
    const int n_h16   = h_elems / 16;
    const int n_tot16 = n_h16 + w_elems / 16;
    cvt_merged_kernel<<<(n_tot16 + 255) / 256, 256>>>(h, fwd_rel, n_h16, n_tot16);

    // Main kernel with programmatic dependent launch: overlap its launch and
    // index loads with the cvt kernel's tail.
    cudaLaunchConfig_t cfg = {};
    cfg.gridDim  = dim3((unsigned)blocks, 1, 1);
    cfg.blockDim = dim3((unsigned)threads, 1, 1);
    cfg.dynamicSmemBytes = 0;
    cfg.stream = 0;
    cudaLaunchAttribute attrs[1];
    attrs[0].id = cudaLaunchAttributeProgrammaticStreamSerialization;
    attrs[0].val.programmaticStreamSerializationAllowed = 1;
    cfg.attrs = attrs;
    cfg.numAttrs = 1;

    cudaError_t err = cudaLaunchKernelEx(&cfg, distmult_fp16_kernel,
                                         src, dst, etype, out, n_edges);
    if (err != cudaSuccess) {
        // PDL unavailable: plain launch (kernel is still correct — the grid
        // dependency sync degenerates to a no-op after full completion).
        distmult_fp16_kernel<<<blocks, threads>>>(src, dst, etype, out, n_edges);
    }
}

// round 17
// speedup vs baseline: 1.0551x; 1.0551x over previous
#include <cuda_runtime.h>
#include <cuda_fp16.h>
#include <cstdint>

// DistMult forward scoring:
//   score[e] = sum_d h[src[e],d] * fwd_rel[etype[e],d] * h[dst[e],d]
// E = 640000, D = 128. Index arrays are int32 on device (JAX x64 disabled).
//
// FINAL (R15 configuration, measured 27.07us, rel_err 5.2877e-4).
// The main kernel runs at the chip-wide LTS byte cap (~340MB @ ~12.8TB/s,
// =6300 B/cyc path-independent). Measured-and-rejected alternatives:
//   - CSR src-grouping: preprocessing (hist/scan/scatter) >= savings (R12/13)
//   - PDL overlap: gridDependencySynchronize adds per-warp ALU cost (R16)
//   - persistent warps / load-shape mixing / higher-MLP cvt: neutral or worse
//   - fp8 storage: aggregate error ~6e-2, fails 1e-3
//
// Structure:
//   1) cvt_merged_kernel: fp32 -> fp16 staging of h and fwd_rel into
//      __device__ scratch (one launch, 16 floats/thread, ~1us).
//   2) distmult_fp16_kernel: 8 lanes/edge, 4 edges/warp; fp16 rows = 256B.
//        h16 -> __ldcg (L2-only; h has ~0.86 row-refs/SM, no L1 value,
//                       and bypassing protects w's L1 residency)
//        w16 -> __ldg  (128KB, L1-resident, ~8.6 refs/row/SM)
//      Math: HMUL2 + HFMA2 fp16x2 accumulation (4 terms deep per element),
//      fp32 final combine, 3-shuffle butterfly, 16B-coalesced store.

#define EMB_DIM   128
#define FULL      0xffffffffu
#define MAX_NODES 16384
#define MAX_RELS  1024

__device__ __half g_h16[MAX_NODES * EMB_DIM];   // 4 MB scratch
__device__ __half g_w16[MAX_RELS  * EMB_DIM];   // 256 KB scratch

// ---- merged fp32 -> fp16 conversion, 16 floats (2 uint4 out) per thread ----
__global__ __launch_bounds__(256) void cvt_merged_kernel(
    const float* __restrict__ h,
    const float* __restrict__ w,
    int n_h16, int n_tot16)
{
    const int i = blockIdx.x * blockDim.x + threadIdx.x;
    if (i >= n_tot16) return;

    const float4* in;
    uint4* out;
    if (i < n_h16) {
        in  = reinterpret_cast<const float4*>(h) + i * 4;
        out = reinterpret_cast<uint4*>(g_h16) + i * 2;
    } else {
        const int j = i - n_h16;
        in  = reinterpret_cast<const float4*>(w) + j * 4;
        out = reinterpret_cast<uint4*>(g_w16) + j * 2;
    }

    // 4 independent streaming loads (MLP=4).
    const float4 v0 = __ldcs(in + 0);
    const float4 v1 = __ldcs(in + 1);
    const float4 v2 = __ldcs(in + 2);
    const float4 v3 = __ldcs(in + 3);

    __half2 p0 = __floats2half2_rn(v0.x, v0.y);
    __half2 p1 = __floats2half2_rn(v0.z, v0.w);
    __half2 p2 = __floats2half2_rn(v1.x, v1.y);
    __half2 p3 = __floats2half2_rn(v1.z, v1.w);
    __half2 p4 = __floats2half2_rn(v2.x, v2.y);
    __half2 p5 = __floats2half2_rn(v2.z, v2.w);
    __half2 p6 = __floats2half2_rn(v3.x, v3.y);
    __half2 p7 = __floats2half2_rn(v3.z, v3.w);

    uint4 o0, o1;
    o0.x = *reinterpret_cast<uint32_t*>(&p0);
    o0.y = *reinterpret_cast<uint32_t*>(&p1);
    o0.z = *reinterpret_cast<uint32_t*>(&p2);
    o0.w = *reinterpret_cast<uint32_t*>(&p3);
    o1.x = *reinterpret_cast<uint32_t*>(&p4);
    o1.y = *reinterpret_cast<uint32_t*>(&p5);
    o1.z = *reinterpret_cast<uint32_t*>(&p6);
    o1.w = *reinterpret_cast<uint32_t*>(&p7);
    out[0] = o0;
    out[1] = o1;
}

// acc2 += (u*w) * v over one uint4 triple (8 halves = 4 half2), all fp16x2.
__device__ __forceinline__ __half2 fma8_h2(uint4 u, uint4 w, uint4 v, __half2 acc2)
{
    const uint32_t* pu = reinterpret_cast<const uint32_t*>(&u);
    const uint32_t* pw = reinterpret_cast<const uint32_t*>(&w);
    const uint32_t* pv = reinterpret_cast<const uint32_t*>(&v);
    #pragma unroll
    for (int k = 0; k < 4; k++) {
        __half2 hu = *reinterpret_cast<const __half2*>(pu + k);
        __half2 hw = *reinterpret_cast<const __half2*>(pw + k);
        __half2 hv = *reinterpret_cast<const __half2*>(pv + k);
        acc2 = __hfma2(__hmul2(hu, hw), hv, acc2);   // 2 instrs per half2
    }
    return acc2;
}

__global__ __launch_bounds__(256, 7) void distmult_fp16_kernel(
    const int* __restrict__ src,
    const int* __restrict__ dst,
    const int* __restrict__ etype,
    float* __restrict__ out,
    int n_edges)
{
    const int warp  = (blockIdx.x * blockDim.x + threadIdx.x) >> 5;
    const int lane  = threadIdx.x & 31;
    const int group = lane >> 3;   // 0..3 : edge within the quad
    const int sl    = lane & 7;    // 0..7 : sub-lane within the edge

    int e = warp * 4 + group;
    const bool valid = (e < n_edges);
    if (warp * 4 >= n_edges) return;
    const int ec = valid ? e : (n_edges - 1);

    const int s = src[ec];
    const int d = dst[ec];
    const int t = etype[ec];

    const uint4* __restrict__ RU =
        reinterpret_cast<const uint4*>(g_h16 + (size_t)s * EMB_DIM);
    const uint4* __restrict__ RV =
        reinterpret_cast<const uint4*>(g_h16 + (size_t)d * EMB_DIM);
    const uint4* __restrict__ RW =
        reinterpret_cast<const uint4*>(g_w16 + (size_t)t * EMB_DIM);

    // Two independent fp16x2 accumulators: each element sums only 4 terms,
    // keeping fp16 accumulation error small; combined once in fp32 below.
    const uint4 au0 = __ldcg(RU + sl);        // h: L2-only
    const uint4 av0 = __ldcg(RV + sl);
    const uint4 aw0 = __ldg (RW + sl);        // rel: L1-resident
    const uint4 au1 = __ldcg(RU + sl + 8);
    const uint4 av1 = __ldcg(RV + sl + 8);
    const uint4 aw1 = __ldg (RW + sl + 8);

    __half2 z = __float2half2_rn(0.0f);
    __half2 acc2a = fma8_h2(au0, aw0, av0, z);
    __half2 acc2b = fma8_h2(au1, aw1, av1, z);

    const float2 fa = __half22float2(acc2a);
    const float2 fb = __half22float2(acc2b);
    float acc = (fa.x + fa.y) + (fb.x + fb.y);

    // Reduce across the 8 sub-lanes of each group.
    acc += __shfl_xor_sync(FULL, acc, 4);
    acc += __shfl_xor_sync(FULL, acc, 2);
    acc += __shfl_xor_sync(FULL, acc, 1);

    if (valid && sl == 0) out[e] = acc;     // 4 contiguous floats / warp
}

// ---- fp32 fallback (R6 kernel) for unexpected dimensions ----
__global__ __launch_bounds__(256, 8) void distmult_fp32_kernel(
    const float* __restrict__ h,
    const int* __restrict__ src,
    const int* __restrict__ dst,
    const int* __restrict__ etype,
    const float* __restrict__ fwd_rel,
    float* __restrict__ out,
    int n_edges)
{
    const int warp  = (blockIdx.x * blockDim.x + threadIdx.x) >> 5;
    const int lane  = threadIdx.x & 31;
    const int group = lane >> 3;
    const int sl    = lane & 7;

    int e = warp * 4 + group;
    const bool valid = (e < n_edges);
    if (warp * 4 >= n_edges) return;
    const int ec = valid ? e : (n_edges - 1);

    const int s = src[ec];
    const int d = dst[ec];
    const int t = etype[ec];

    const float4* __restrict__ hu = reinterpret_cast<const float4*>(h + (size_t)s * EMB_DIM);
    const float4* __restrict__ hv = reinterpret_cast<const float4*>(h + (size_t)d * EMB_DIM);
    const float4* __restrict__ wr = reinterpret_cast<const float4*>(fwd_rel + (size_t)t * EMB_DIM);

    float acc = 0.0f;
    #pragma unroll
    for (int j = 0; j < 4; j++) {
        const int idx = sl + j * 8;
        const float4 a = __ldcg(hu + idx);
        const float4 c = __ldcg(hv + idx);
        const float4 b = __ldg(wr + idx);
        float p = a.x * b.x * c.x;
        p = fmaf(a.y * b.y, c.y, p);
        p = fmaf(a.z * b.z, c.z, p);
        p = fmaf(a.w * b.w, c.w, p);
        acc += p;
    }
    acc += __shfl_xor_sync(FULL, acc, 4);
    acc += __shfl_xor_sync(FULL, acc, 2);
    acc += __shfl_xor_sync(FULL, acc, 1);
    if (valid && sl == 0) out[e] = acc;
}

extern "C" void kernel_launch(void* const* d_in, const int* in_sizes, int n_in,
                              void* d_out, int out_size)
{
    const float* h       = (const float*)d_in[0];
    const int*   src     = (const int*)d_in[1];
    const int*   dst     = (const int*)d_in[2];
    const int*   etype   = (const int*)d_in[3];
    const float* fwd_rel = (const float*)d_in[4];
    // d_in[5] = rev_rel, unused in forward scoring.
    float* out = (float*)d_out;

    const int n_edges = in_sizes[1];   // src element count
    const int h_elems = in_sizes[0];   // n_nodes * 128
    const int w_elems = in_sizes[4];   // num_rels * 128

    const int threads = 256;
    const int blocks  = (n_edges + 31) / 32;   // 8 warps x 4 edges per block

    if (h_elems > MAX_NODES * EMB_DIM || w_elems > MAX_RELS * EMB_DIM ||
        (h_elems & 15) || (w_elems & 15)) {
        // Unexpected dims: proven fp32 path.
        distmult_fp32_kernel<<<blocks, threads>>>(h, src, dst, etype, fwd_rel,
                                                  out, n_edges);
        return;
    }

    // Prologue: merged fp32 -> fp16 staging (one launch, 16 floats/thread).
    const int n_h16   = h_elems / 16;
    const int n_tot16 = n_h16 + w_elems / 16;
    cvt_merged_kernel<<<(n_tot16 + 255) / 256, 256>>>(h, fwd_rel, n_h16, n_tot16);

    distmult_fp16_kernel<<<blocks, threads>>>(src, dst, etype, out, n_edges);
}